// round 9
// baseline (speedup 1.0000x reference)
#include <cuda_runtime.h>
#include <cuda_fp16.h>
#include <cstdint>

#define B_   64
#define N_   64
#define C_   8
#define F_   256
#define CF   2048   // C_*F_
#define OCOF 2048   // OC*OF
#define MROWS 4224  // 4096 zn rows + 64 zx rows + 64 zero pad

// ---- scratch (static device arrays; zero-initialized at module load) ----
__device__ float d_s1[B_];
__device__ float d_s2[B_ * N_];
__device__ float d_t[B_ * C_ * F_];
__device__ __half d_denomh[B_ * F_ * F_];      // RECIPROCAL of denom, fp16
__device__ __half d_Zh[(size_t)MROWS * CF];    // fp16 zn/zx; pad rows stay 0
__device__ __half d_Wch[(size_t)OCOF * CF];    // fp16 copy of Wc

__device__ __forceinline__ uint32_t smem_u32(const void* p) {
    uint32_t a;
    asm("{ .reg .u64 t; cvta.to.shared.u64 t, %1; cvt.u32.u64 %0, t; }" : "=r"(a) : "l"(p));
    return a;
}
__device__ __forceinline__ void ldsm4(uint32_t& r0, uint32_t& r1, uint32_t& r2, uint32_t& r3,
                                      uint32_t addr) {
    asm volatile("ldmatrix.sync.aligned.m8n8.x4.shared.b16 {%0,%1,%2,%3}, [%4];"
                 : "=r"(r0), "=r"(r1), "=r"(r2), "=r"(r3) : "r"(addr));
}
__device__ __forceinline__ void cp16(uint32_t dst, const void* src) {
    asm volatile("cp.async.cg.shared.global [%0], [%1], 16;" :: "r"(dst), "l"(src));
}

// ============================ K1: s1/s2 (wsum fused) ============================
__global__ void k_s12(const float* __restrict__ x, const float* __restrict__ nb,
                      const float* __restrict__ W1, const float* __restrict__ W2) {
    __shared__ float red[256];
    int bid = blockIdx.x;
    int tid = threadIdx.x;
    const float* src;
    const float* W;
    if (bid < B_) { src = x + (size_t)bid * CF;          W = W1; }
    else          { src = nb + (size_t)(bid - B_) * CF;  W = W2; }
    float ws = 0.f;
#pragma unroll
    for (int k = 0; k < C_; k++) ws += W[k * F_ + tid];
    float acc = 0.f;
#pragma unroll
    for (int i = 0; i < C_; i++) acc += src[i * F_ + tid] * ws;
    red[tid] = acc; __syncthreads();
    for (int s = 128; s > 0; s >>= 1) { if (tid < s) red[tid] += red[tid + s]; __syncthreads(); }
    if (tid == 0) { if (bid < B_) d_s1[bid] = red[0]; else d_s2[bid - B_] = red[0]; }
}

__global__ void k_t(const float* __restrict__ nb) {
    int b = blockIdx.x >> 3, c = blockIdx.x & 7;
    int d = threadIdx.x;
    __shared__ float ws[N_];
    if (d < N_) ws[d] = d_s1[b] * d_s2[b * N_ + d];
    __syncthreads();
    const float* base = nb + (((size_t)b * N_) * C_ + c) * F_ + d;
    float acc = 0.f;
#pragma unroll 8
    for (int n = 0; n < N_; n++) acc += base[(size_t)n * CF] * ws[n];
    d_t[(b * C_ + c) * F_ + d] = acc;
}

__device__ __forceinline__ float sgnroot_abs(float v) {
    return (v == 0.f) ? 0.f : sqrtf(fmaxf(fabsf(v), 1e-8f));
}
__device__ __forceinline__ float sgnroot(float v) {
    return (v == 0.f) ? 0.f : copysignf(sqrtf(fmaxf(fabsf(v), 1e-8f)), v);
}

__global__ void k_denom(const float* __restrict__ x) {
    int b = blockIdx.y;
    int slice = blockIdx.x;
    int tid = threadIdx.x;
    __shared__ float xs[CF], ts[CF];
#pragma unroll
    for (int j = 0; j < 8; j++) {
        xs[tid + j * 256] = x[(size_t)b * CF + tid + j * 256];
        ts[tid + j * 256] = d_t[(size_t)b * CF + tid + j * 256];
    }
    __syncthreads();
    int d = tid;
    for (int ai = 0; ai < 16; ai++) {
        int a = slice * 16 + ai;
        float acc = 0.f;
#pragma unroll
        for (int c = 0; c < C_; c++) {
            float v = xs[c * F_ + a] * ts[c * F_ + d] + xs[c * F_ + d] * ts[c * F_ + a];
            acc += sgnroot_abs(v);
        }
        d_denomh[((size_t)b * F_ + a) * F_ + d] = __float2half_rn(__fdividef(1.f, acc + 1e-7f));
    }
}

// ============================ K5: fp16 tensor-core zn/zx ============================
#define APITCH 40   // halves
__global__ void __launch_bounds__(256, 2) k_zn_mma(const float* __restrict__ x,
                                                   const float* __restrict__ nb) {
    int b = blockIdx.x >> 3, c = blockIdx.x & 7;
    int tid = threadIdx.x;
    int wid = tid >> 5, lid = tid & 31;
    int g = lid >> 2, tig = lid & 3;
    int A0 = wid * 32;

    __shared__ float xS[F_], tS[F_];
    __shared__ __half adjS[F_][APITCH];
    __shared__ __half nbS[64][APITCH];

    xS[tid] = x[(size_t)(b * C_ + c) * F_ + tid];
    tS[tid] = d_t[(size_t)(b * C_ + c) * F_ + tid];
    __syncthreads();

    float acc[4][4][4];
#pragma unroll
    for (int i = 0; i < 4; i++)
#pragma unroll
        for (int j = 0; j < 4; j++)
#pragma unroll
            for (int k = 0; k < 4; k++) acc[i][j][k] = 0.f;
    float zxAcc = 0.f;

    const int dl = tid & 31;
    const int w8 = tid >> 5;

    const uint32_t nbBase = smem_u32(nbS) + ((uint32_t)((lid & 15) * APITCH + (lid >> 4) * 8)) * 2;
    const uint32_t adjBase = smem_u32(adjS) +
        ((uint32_t)((A0 + ((lid >> 4) & 1) * 8 + (lid & 7)) * APITCH + ((lid >> 3) & 1) * 8)) * 2;

    for (int dt = 0; dt < 8; dt++) {
        const int d0 = dt * 32;
        const float xd = xS[d0 + dl], td = tS[d0 + dl];
        const __half* rden = d_denomh + (size_t)b * F_ * F_ + d0 + dl;
#pragma unroll
        for (int j = 0; j < 32; j++) {
            int a = w8 + j * 8;
            float v = xS[a] * td + xd * tS[a];
            float gg = sgnroot(v);
            adjS[a][dl] = __float2half_rn(gg * __half2float(rden[(size_t)a * F_]));
        }
#pragma unroll
        for (int j = 0; j < 8; j++) {
            int i = tid + j * 256;
            int n = i >> 5, d2 = i & 31;
            nbS[n][d2] = __float2half_rn(nb[((((size_t)b * N_) + n) * C_ + c) * F_ + d0 + d2]);
        }
        __syncthreads();

#pragma unroll
        for (int ks = 0; ks < 2; ks++) {
            const int kb = ks * 16;
            uint32_t a4[4][4], b2[4][2];
#pragma unroll
            for (int mt = 0; mt < 4; mt++)
                ldsm4(a4[mt][0], a4[mt][1], a4[mt][2], a4[mt][3],
                      nbBase + (uint32_t)(mt * 16 * APITCH + kb) * 2);
#pragma unroll
            for (int p = 0; p < 2; p++)
                ldsm4(b2[2 * p][0], b2[2 * p][1], b2[2 * p + 1][0], b2[2 * p + 1][1],
                      adjBase + (uint32_t)(p * 16 * APITCH + kb) * 2);
#pragma unroll
            for (int mt = 0; mt < 4; mt++)
#pragma unroll
                for (int nt = 0; nt < 4; nt++) {
                    asm volatile(
                        "mma.sync.aligned.m16n8k16.row.col.f32.f16.f16.f32 "
                        "{%0,%1,%2,%3}, {%4,%5,%6,%7}, {%8,%9}, {%0,%1,%2,%3};"
                        : "+f"(acc[mt][nt][0]), "+f"(acc[mt][nt][1]),
                          "+f"(acc[mt][nt][2]), "+f"(acc[mt][nt][3])
                        : "r"(a4[mt][0]), "r"(a4[mt][1]), "r"(a4[mt][2]), "r"(a4[mt][3]),
                          "r"(b2[nt][0]), "r"(b2[nt][1]));
                }
        }
        {
            int a = A0 + lid;
#pragma unroll
            for (int k2 = 0; k2 < 32; k2++) zxAcc += __half2float(adjS[a][k2]) * xS[d0 + k2];
        }
        __syncthreads();
    }

#pragma unroll
    for (int mt = 0; mt < 4; mt++) {
#pragma unroll
        for (int half = 0; half < 2; half++) {
            int n = mt * 16 + g + half * 8;
            __half* dst = d_Zh + ((((size_t)b * N_) + n) * C_ + c) * F_;
#pragma unroll
            for (int nt = 0; nt < 4; nt++) {
                int col = A0 + nt * 8 + 2 * tig;
                __half2 v = __floats2half2_rn(acc[mt][nt][half * 2], acc[mt][nt][half * 2 + 1]);
                *(__half2*)(dst + col) = v;
            }
        }
    }
    d_Zh[(size_t)(4096 + b) * CF + c * F_ + A0 + lid] = __float2half_rn(zxAcc);
}

// Convert Wc to fp16 (8 floats / thread)
__global__ void k_wc(const float* __restrict__ Wc) {
    size_t i = ((size_t)blockIdx.x * 256 + threadIdx.x) * 8;
    float4 v0 = *(const float4*)(Wc + i);
    float4 v1 = *(const float4*)(Wc + i + 4);
    __half2 h[4];
    h[0] = __floats2half2_rn(v0.x, v0.y);
    h[1] = __floats2half2_rn(v0.z, v0.w);
    h[2] = __floats2half2_rn(v1.x, v1.y);
    h[3] = __floats2half2_rn(v1.z, v1.w);
    *(uint4*)(d_Wch + i) = *(const uint4*)h;
}

// ============================ K6: fp16 mma GEMM, 4 warps x (64x64), 3-stage ============================
#define PITCHH 72
#define BUFH (128 * PITCHH)                // halves per operand per stage
#define STAGE_B (2 * BUFH * 2)             // bytes per stage (A+B)
#define GEMM_SMEM (3 * STAGE_B)

__global__ void __launch_bounds__(128, 2) k_gemm_mma(float* __restrict__ out) {
    extern __shared__ __half smh[];
    const int tid = threadIdx.x;
    const int wid = tid >> 5, lid = tid & 31;
    const int wm = wid >> 1, wn = wid & 1;     // 2x2 grid of 64x64 warp tiles
    const int g = lid >> 2, tig = lid & 3;
    const int bm = blockIdx.y * 128, bo = blockIdx.x * 128;

    const int lrow = tid >> 3;                 // 0..15
    const int jc = tid & 7;
    const uint32_t sBase = smem_u32(smh);
    const __half* Ag = d_Zh + (size_t)(bm + lrow) * CF + jc * 8;
    const __half* Bg = d_Wch + (size_t)(bo + lrow) * CF + jc * 8;
    const uint32_t swOff = (uint32_t)(lrow * PITCHH + jc * 8) * 2;

    // ldmatrix lane bases (stage 0)
    const uint32_t aBase = sBase + ((uint32_t)((wm * 64 + (lid & 15)) * PITCHH + (lid >> 4) * 8)) * 2;
    const uint32_t bBase = sBase + (uint32_t)BUFH * 2 +
        ((uint32_t)((wn * 64 + ((lid >> 4) & 1) * 8 + (lid & 7)) * PITCHH + ((lid >> 3) & 1) * 8)) * 2;

    float acc[4][8][4];
#pragma unroll
    for (int i = 0; i < 4; i++)
#pragma unroll
        for (int j = 0; j < 8; j++)
#pragma unroll
            for (int k = 0; k < 4; k++) acc[i][j][k] = 0.f;

    const int NKT = CF / 64;   // 32

    auto load_stage = [&](int stg, int kt) {
        uint32_t dA = sBase + (uint32_t)stg * STAGE_B + swOff;
        uint32_t dB = dA + (uint32_t)BUFH * 2;
        const __half* As = Ag + kt * 64;
        const __half* Bs = Bg + kt * 64;
#pragma unroll
        for (int p = 0; p < 8; p++) {
            cp16(dA + p * 16 * PITCHH * 2, As + (size_t)p * 16 * CF);
            cp16(dB + p * 16 * PITCHH * 2, Bs + (size_t)p * 16 * CF);
        }
        asm volatile("cp.async.commit_group;" ::: "memory");
    };

    load_stage(0, 0);
    load_stage(1, 1);

    int stg = 0;
    for (int kt = 0; kt < NKT; kt++) {
        if (kt == NKT - 1) asm volatile("cp.async.wait_group 0;" ::: "memory");
        else               asm volatile("cp.async.wait_group 1;" ::: "memory");
        __syncthreads();
        if (kt + 2 < NKT) {
            int ns = stg + 2; if (ns >= 3) ns -= 3;
            load_stage(ns, kt + 2);
        }
        const uint32_t aB = aBase + (uint32_t)stg * STAGE_B;
        const uint32_t bB = bBase + (uint32_t)stg * STAGE_B;
#pragma unroll
        for (int ks = 0; ks < 4; ks++) {
            const uint32_t kOff = (uint32_t)(ks * 16) * 2;
            uint32_t a[4][4], b[8][2];
#pragma unroll
            for (int mt = 0; mt < 4; mt++)
                ldsm4(a[mt][0], a[mt][1], a[mt][2], a[mt][3],
                      aB + (uint32_t)(mt * 16 * PITCHH) * 2 + kOff);
#pragma unroll
            for (int p = 0; p < 4; p++)
                ldsm4(b[2 * p][0], b[2 * p][1], b[2 * p + 1][0], b[2 * p + 1][1],
                      bB + (uint32_t)(p * 16 * PITCHH) * 2 + kOff);
#pragma unroll
            for (int mt = 0; mt < 4; mt++)
#pragma unroll
                for (int nt = 0; nt < 8; nt++) {
                    asm volatile(
                        "mma.sync.aligned.m16n8k16.row.col.f32.f16.f16.f32 "
                        "{%0,%1,%2,%3}, {%4,%5,%6,%7}, {%8,%9}, {%0,%1,%2,%3};"
                        : "+f"(acc[mt][nt][0]), "+f"(acc[mt][nt][1]),
                          "+f"(acc[mt][nt][2]), "+f"(acc[mt][nt][3])
                        : "r"(a[mt][0]), "r"(a[mt][1]), "r"(a[mt][2]), "r"(a[mt][3]),
                          "r"(b[nt][0]), "r"(b[nt][1]));
                }
        }
        if (++stg == 3) stg = 0;
    }

#pragma unroll
    for (int mt = 0; mt < 4; mt++) {
#pragma unroll
        for (int half = 0; half < 2; half++) {
            int m = bm + wm * 64 + mt * 16 + g + half * 8;
            float* dst;
            if (m < 4096)      dst = out + (size_t)B_ * OCOF + (size_t)m * OCOF;
            else if (m < 4160) dst = out + (size_t)(m - 4096) * OCOF;
            else               continue;
#pragma unroll
            for (int nt = 0; nt < 8; nt++) {
                int col = bo + wn * 64 + nt * 8 + 2 * tig;
                float2 v = make_float2(acc[mt][nt][half * 2], acc[mt][nt][half * 2 + 1]);
                *(float2*)(dst + col) = v;
            }
        }
    }
}

// ============================ launch ============================
extern "C" void kernel_launch(void* const* d_in, const int* in_sizes, int n_in,
                              void* d_out, int out_size) {
    (void)in_sizes; (void)n_in; (void)out_size;
    const float* x  = (const float*)d_in[0];
    const float* nb = (const float*)d_in[1];
    const float* W1 = (const float*)d_in[2];
    const float* W2 = (const float*)d_in[3];
    const float* Wc = (const float*)d_in[4];
    float* out = (float*)d_out;

    cudaFuncSetAttribute(k_gemm_mma, cudaFuncAttributeMaxDynamicSharedMemorySize, GEMM_SMEM);

    k_s12<<<B_ + B_ * N_, 256>>>(x, nb, W1, W2);
    k_t<<<B_ * C_, 256>>>(nb);
    k_denom<<<dim3(16, B_), 256>>>(x);
    k_wc<<<(OCOF * CF) / 2048, 256>>>(Wc);
    k_zn_mma<<<B_ * C_, 256>>>(x, nb);
    k_gemm_mma<<<dim3(OCOF / 128, MROWS / 128), 128, GEMM_SMEM>>>(out);
}